// round 1
// baseline (speedup 1.0000x reference)
#include <cuda_runtime.h>
#include <cstdint>

#define PAD 16
#define H 256
#define W 256
#define HO 288
#define WO 288
#define NLAM 96
#define NB 4
#define NK 4
#define NCHUNK 2
#define LCHUNK (NLAM / NCHUNK)   // 48
#define TILE 32
#define REGROWS 64
#define RSTRIDE 65

#define KS 15
#define KR 7
#define CTILE 32
#define CREG 46                  // 32 + 14
#define CSTRIDE 47

// Partial accumulators: [chunk][b*4+k][HO][WO]  (2 * 16 * 288*288 * 4B = 10.6 MB)
__device__ float g_part[NCHUNK * NB * NK * HO * WO];

struct WInfo {
    float w00, w01, w10, w11;
    int oy, ox;
};

// ---------------------------------------------------------------------------
// Pass 1: for each (b, lambda-chunk) and 32x32 output tile, accumulate the
// bilinear-shifted cube over lambda for all 4 k-sequences at once.
// Per lambda the shift is plane-uniform: integer offset + 4 weights.
// ---------------------------------------------------------------------------
__global__ void __launch_bounds__(256)
shift_acc_kernel(const float* __restrict__ cube,
                 const float* __restrict__ dxv,
                 const float* __restrict__ dyv)
{
    __shared__ float s_img[REGROWS * RSTRIDE];          // 16.6 KB
    __shared__ WInfo s_wt[LCHUNK * NK];                 // 4.6 KB
    __shared__ short s_oymin[LCHUNK], s_oxmin[LCHUNK];
    __shared__ short s_rn[LCHUNK], s_cn[LCHUNK];
    __shared__ unsigned char s_ok[LCHUNK];

    const int tid   = threadIdx.x;
    const int bz    = blockIdx.z;           // b * NCHUNK + chunk
    const int b     = bz >> 1;
    const int chunk = bz & 1;
    const int lam0  = chunk * LCHUNK;
    const int x0    = blockIdx.x * TILE;
    const int y0    = blockIdx.y * TILE;

    // --- Precompute per-(lambda,k) integer offsets + bilinear weights ---
    for (int i = tid; i < LCHUNK * NK; i += 256) {
        const int l   = i >> 2;
        const int k   = i & 3;
        const int lam = lam0 + l;
        const float sx = -dxv[k * NLAM + lam] - (float)PAD;
        const float sy = -dyv[k * NLAM + lam] - (float)PAD;
        const float fox = floorf(sx), foy = floorf(sy);
        const float fx = sx - fox, fy = sy - foy;
        WInfo wi;
        wi.ox = (int)fox;
        wi.oy = (int)foy;
        const float gxw = 1.f - fx, gyw = 1.f - fy;
        wi.w00 = gyw * gxw;
        wi.w01 = gyw * fx;
        wi.w10 = fy * gxw;
        wi.w11 = fy * fx;
        s_wt[i] = wi;
    }
    __syncthreads();

    // --- Per-lambda union bounding box over the 4 k offsets ---
    for (int l = tid; l < LCHUNK; l += 256) {
        int oymin = s_wt[l * 4].oy, oymax = oymin;
        int oxmin = s_wt[l * 4].ox, oxmax = oxmin;
#pragma unroll
        for (int k = 1; k < NK; ++k) {
            const int oy = s_wt[l * 4 + k].oy;
            const int ox = s_wt[l * 4 + k].ox;
            oymin = min(oymin, oy); oymax = max(oymax, oy);
            oxmin = min(oxmin, ox); oxmax = max(oxmax, ox);
        }
        const int rn = TILE + 1 + (oymax - oymin);
        const int cn = TILE + 1 + (oxmax - oxmin);
        s_oymin[l] = (short)oymin;
        s_oxmin[l] = (short)oxmin;
        s_rn[l]    = (short)rn;
        s_cn[l]    = (short)cn;
        s_ok[l]    = (rn <= REGROWS && cn <= REGROWS) ? 1 : 0;
    }
    __syncthreads();

    const int lane = tid & 31;
    const int warp = tid >> 5;   // 8 warps; warp covers output rows y0+4w .. y0+4w+3
    const int yb   = 4 * warp;

    float acc[NK][4];
#pragma unroll
    for (int k = 0; k < NK; ++k)
#pragma unroll
        for (int r = 0; r < 4; ++r) acc[k][r] = 0.f;

    const float* imgb = cube + (size_t)(b * NLAM + lam0) * (H * W);

    for (int l = 0; l < LCHUNK; ++l) {
        const float* img = imgb + (size_t)l * (H * W);
        const int oym = s_oymin[l];
        const int oxm = s_oxmin[l];
        const bool ok = (s_ok[l] != 0);
        const int rn = s_rn[l];
        const int cn = s_cn[l];

        __syncthreads();   // previous iteration's compute done before reload
        if (ok) {
            const int gy0 = y0 + oym;
            const int gx0 = x0 + oxm;
            const int c   = tid & 63;
            const int r0f = tid >> 6;
            if (c < cn) {
                const int gx = gx0 + c;
                const bool xok = (unsigned)gx < (unsigned)W;
                for (int r = r0f; r < rn; r += 4) {
                    const int gy = gy0 + r;
                    float v = 0.f;
                    if (xok && (unsigned)gy < (unsigned)H)
                        v = __ldg(&img[gy * W + gx]);
                    s_img[r * RSTRIDE + c] = v;
                }
            }
        }
        __syncthreads();

#pragma unroll
        for (int k = 0; k < NK; ++k) {
            const WInfo wi = s_wt[l * 4 + k];
            if (ok) {
                const int oyr = wi.oy - oym;
                const int oxr = wi.ox - oxm;
                const int rowbase = (yb + oyr) * RSTRIDE + oxr;
                float a[5], bb[5];
#pragma unroll
                for (int r = 0; r < 5; ++r) {
                    const float av = s_img[rowbase + r * RSTRIDE + lane];
                    const float ev = s_img[rowbase + r * RSTRIDE + 32];   // broadcast
                    const float bv = __shfl_down_sync(0xffffffffu, av, 1);
                    a[r]  = av;
                    bb[r] = (lane == 31) ? ev : bv;
                }
#pragma unroll
                for (int r = 0; r < 4; ++r) {
                    acc[k][r] += wi.w00 * a[r]   + wi.w01 * bb[r]
                               + wi.w10 * a[r+1] + wi.w11 * bb[r+1];
                }
            } else {
                // Rare fallback: offsets too spread for the smem tile — sample global.
                const int px = x0 + lane;
#pragma unroll
                for (int r = 0; r < 4; ++r) {
                    const int py  = y0 + yb + r;
                    const int iy0 = py + wi.oy;
                    const int ix0 = px + wi.ox;
                    const bool y0ok = (unsigned)iy0       < (unsigned)H;
                    const bool y1ok = (unsigned)(iy0 + 1) < (unsigned)H;
                    const bool x0ok = (unsigned)ix0       < (unsigned)W;
                    const bool x1ok = (unsigned)(ix0 + 1) < (unsigned)W;
                    const float v00 = (y0ok && x0ok) ? __ldg(&img[iy0 * W + ix0])           : 0.f;
                    const float v01 = (y0ok && x1ok) ? __ldg(&img[iy0 * W + ix0 + 1])       : 0.f;
                    const float v10 = (y1ok && x0ok) ? __ldg(&img[(iy0 + 1) * W + ix0])     : 0.f;
                    const float v11 = (y1ok && x1ok) ? __ldg(&img[(iy0 + 1) * W + ix0 + 1]) : 0.f;
                    acc[k][r] += wi.w00 * v00 + wi.w01 * v01 + wi.w10 * v10 + wi.w11 * v11;
                }
            }
        }
    }

    // --- Write partials ---
    float* gp = g_part + (size_t)chunk * (NB * NK * HO * WO)
                       + (size_t)b * (NK * HO * WO);
#pragma unroll
    for (int k = 0; k < NK; ++k) {
#pragma unroll
        for (int r = 0; r < 4; ++r) {
            gp[(size_t)k * (HO * WO) + (y0 + yb + r) * WO + x0 + lane] = acc[k][r];
        }
    }
}

// ---------------------------------------------------------------------------
// Pass 2: 15x15 PSF convolution on the 16 (b,k) planes, summing the 2 chunks.
// smem-tiled 46x46 region, 2x2 register patch per thread, FMA-pipe bound.
// ---------------------------------------------------------------------------
__global__ void __launch_bounds__(256)
psf_conv_kernel(const float* __restrict__ psf, float* __restrict__ out)
{
    __shared__ float s_acc[CREG * CSTRIDE];   // 8.65 KB
    __shared__ float s_psf[KS * KS];

    const int tid = threadIdx.x;
    const int p   = blockIdx.z;               // plane: b*4+k
    const int x0  = blockIdx.x * CTILE;
    const int y0  = blockIdx.y * CTILE;

    if (tid < KS * KS) s_psf[tid] = __ldg(&psf[tid]);

    const float* p0 = g_part + (size_t)p * (HO * WO);
    const float* p1 = p0 + (size_t)(NB * NK) * (HO * WO);

    for (int i = tid; i < CREG * CREG; i += 256) {
        const int r  = i / CREG;
        const int c  = i - r * CREG;
        const int gy = y0 + r - KR;
        const int gx = x0 + c - KR;
        float v = 0.f;
        if ((unsigned)gy < (unsigned)HO && (unsigned)gx < (unsigned)WO) {
            const int idx = gy * WO + gx;
            v = __ldg(&p0[idx]) + __ldg(&p1[idx]);
        }
        s_acc[r * CSTRIDE + c] = v;
    }
    __syncthreads();

    const int tx = (tid & 15) * 2;
    const int ty = (tid >> 4) * 2;

    float o00 = 0.f, o01 = 0.f, o10 = 0.f, o11 = 0.f;
#pragma unroll 1
    for (int u = 0; u < KS; ++u) {
        const float* srow0 = &s_acc[(ty + u) * CSTRIDE + tx];
        const float* srow1 = srow0 + CSTRIDE;
        const float* wrow  = &s_psf[u * KS];
        float c0a = srow0[0];
        float c0b = srow1[0];
#pragma unroll
        for (int v = 0; v < KS; ++v) {
            const float w   = wrow[v];
            const float c1a = srow0[v + 1];
            const float c1b = srow1[v + 1];
            o00 += w * c0a;
            o01 += w * c1a;
            o10 += w * c0b;
            o11 += w * c1b;
            c0a = c1a;
            c0b = c1b;
        }
    }

    float* op = out + (size_t)p * (HO * WO) + (y0 + ty) * WO + x0 + tx;
    op[0]      = o00;
    op[1]      = o01;
    op[WO]     = o10;
    op[WO + 1] = o11;
}

// ---------------------------------------------------------------------------
extern "C" void kernel_launch(void* const* d_in, const int* in_sizes, int n_in,
                              void* d_out, int out_size)
{
    const float* cube = (const float*)d_in[0];   // (4, 96, 256, 256)
    const float* dx   = (const float*)d_in[1];   // (4, 96)
    const float* dy   = (const float*)d_in[2];   // (4, 96)
    const float* psf  = (const float*)d_in[3];   // (15, 15)
    float* out        = (float*)d_out;           // (4, 4, 288, 288)

    dim3 g1(WO / TILE, HO / TILE, NB * NCHUNK);  // 9 x 9 x 8
    shift_acc_kernel<<<g1, 256>>>(cube, dx, dy);

    dim3 g2(WO / CTILE, HO / CTILE, NB * NK);    // 9 x 9 x 16
    psf_conv_kernel<<<g2, 256>>>(psf, out);
}

// round 2
// speedup vs baseline: 1.5933x; 1.5933x over previous
#include <cuda_runtime.h>
#include <cstdint>

#define PAD 16
#define H 256
#define W 256
#define HO 288
#define WO 288
#define NLAM 96
#define NB 4
#define NK 4
#define NCHUNK 2
#define LCHUNK (NLAM / NCHUNK)   // 48
#define TILE 32
#define REGROWS 64
#define RSTRIDE 65

#define KS 15
#define KR 7

// Partial accumulators: [chunk][b*4+k][HO][WO]  (2 * 16 * 288*288 * 4B = 10.6 MB)
__device__ float g_part[NCHUNK * NB * NK * HO * WO];

struct WInfo {
    float w00, w01, w10, w11;
    int oy, ox;
};

typedef unsigned long long ull;

__device__ __forceinline__ ull pack2(float lo, float hi) {
    ull r;
    asm("mov.b64 %0, {%1, %2};" : "=l"(r) : "f"(lo), "f"(hi));
    return r;
}
__device__ __forceinline__ void fma2(ull& d, ull a, ull b) {
    asm("fma.rn.f32x2 %0, %1, %2, %3;" : "=l"(d) : "l"(a), "l"(b), "l"(d));
}
__device__ __forceinline__ void unpack2(ull v, float& lo, float& hi) {
    asm("mov.b64 {%0, %1}, %2;" : "=f"(lo), "=f"(hi) : "l"(v));
}

// ---------------------------------------------------------------------------
// Pass 1: bilinear shift-accumulate over lambda for all 4 k-sequences.
// Double-buffered smem tile, one __syncthreads per lambda, no SHFL.
// ---------------------------------------------------------------------------
__device__ __forceinline__ void fill_buf(float* __restrict__ buf,
                                         const float* __restrict__ img,
                                         int gy0, int gx0, int rn, int tid)
{
    const int c  = tid & 63;
    const int r0 = tid >> 6;
    const int gx = gx0 + c;
    const bool xok = (unsigned)gx < (unsigned)W;
#pragma unroll 4
    for (int r = r0; r < rn; r += 4) {
        const int gy = gy0 + r;
        float v = 0.f;
        if (xok && (unsigned)gy < (unsigned)H)
            v = __ldg(&img[gy * W + gx]);
        buf[r * RSTRIDE + c] = v;
    }
}

__global__ void __launch_bounds__(256)
shift_acc_kernel(const float* __restrict__ cube,
                 const float* __restrict__ dxv,
                 const float* __restrict__ dyv)
{
    __shared__ float s_img[2][REGROWS * RSTRIDE];       // 2 x 16.6 KB
    __shared__ WInfo s_wt[LCHUNK * NK];                 // 4.6 KB
    __shared__ short s_oymin[LCHUNK], s_oxmin[LCHUNK];
    __shared__ short s_rn[LCHUNK];
    __shared__ unsigned char s_okf[LCHUNK];

    const int tid   = threadIdx.x;
    const int bz    = blockIdx.z;           // b * NCHUNK + chunk
    const int b     = bz >> 1;
    const int chunk = bz & 1;
    const int lam0  = chunk * LCHUNK;
    const int x0    = blockIdx.x * TILE;
    const int y0    = blockIdx.y * TILE;

    // --- Precompute per-(lambda,k) integer offsets + bilinear weights ---
    for (int i = tid; i < LCHUNK * NK; i += 256) {
        const int l   = i >> 2;
        const int k   = i & 3;
        const int lam = lam0 + l;
        const float sx = -dxv[k * NLAM + lam] - (float)PAD;
        const float sy = -dyv[k * NLAM + lam] - (float)PAD;
        const float fox = floorf(sx), foy = floorf(sy);
        const float fx = sx - fox, fy = sy - foy;
        WInfo wi;
        wi.ox = (int)fox;
        wi.oy = (int)foy;
        const float gxw = 1.f - fx, gyw = 1.f - fy;
        wi.w00 = gyw * gxw;
        wi.w01 = gyw * fx;
        wi.w10 = fy * gxw;
        wi.w11 = fy * fx;
        s_wt[i] = wi;
    }
    __syncthreads();

    // --- Per-lambda union bounding box over the 4 k offsets ---
    for (int l = tid; l < LCHUNK; l += 256) {
        int oymin = s_wt[l * 4].oy, oymax = oymin;
        int oxmin = s_wt[l * 4].ox, oxmax = oxmin;
#pragma unroll
        for (int k = 1; k < NK; ++k) {
            const int oy = s_wt[l * 4 + k].oy;
            const int ox = s_wt[l * 4 + k].ox;
            oymin = min(oymin, oy); oymax = max(oymax, oy);
            oxmin = min(oxmin, ox); oxmax = max(oxmax, ox);
        }
        const int rn = TILE + 1 + (oymax - oymin);
        const int cn = TILE + 1 + (oxmax - oxmin);
        s_oymin[l] = (short)oymin;
        s_oxmin[l] = (short)oxmin;
        s_rn[l]    = (short)rn;
        s_okf[l]   = (rn <= REGROWS && cn <= REGROWS) ? 1 : 0;
    }
    __syncthreads();

    const int lane = tid & 31;
    const int warp = tid >> 5;   // 8 warps; warp covers output rows y0+4w .. y0+4w+3
    const int yb   = 4 * warp;

    float acc[NK][4];
#pragma unroll
    for (int k = 0; k < NK; ++k)
#pragma unroll
        for (int r = 0; r < 4; ++r) acc[k][r] = 0.f;

    const float* imgb = cube + (size_t)(b * NLAM + lam0) * (H * W);

    // Prologue: fill buffer 0 for lambda 0
    if (s_okf[0])
        fill_buf(s_img[0], imgb, y0 + s_oymin[0], x0 + s_oxmin[0], s_rn[0], tid);

    for (int l = 0; l < LCHUNK; ++l) {
        __syncthreads();   // fill(l) visible; compute(l-1) done so buf[(l+1)&1] is free

        // Issue next fill first so its LDGs overlap this lambda's compute.
        if (l + 1 < LCHUNK && s_okf[l + 1]) {
            fill_buf(s_img[(l + 1) & 1], imgb + (size_t)(l + 1) * (H * W),
                     y0 + s_oymin[l + 1], x0 + s_oxmin[l + 1], s_rn[l + 1], tid);
        }

        const float* img = imgb + (size_t)l * (H * W);
        const float* buf = s_img[l & 1];
        const int oym = s_oymin[l];
        const int oxm = s_oxmin[l];
        const bool ok = (s_okf[l] != 0);

#pragma unroll
        for (int k = 0; k < NK; ++k) {
            const WInfo wi = s_wt[l * 4 + k];
            if (ok) {
                const int rowbase = (yb + wi.oy - oym) * RSTRIDE + (wi.ox - oxm) + lane;
                float a[5], bb[5];
#pragma unroll
                for (int r = 0; r < 5; ++r) {
                    a[r]  = buf[rowbase + r * RSTRIDE];
                    bb[r] = buf[rowbase + r * RSTRIDE + 1];
                }
#pragma unroll
                for (int r = 0; r < 4; ++r) {
                    acc[k][r] += wi.w00 * a[r]   + wi.w01 * bb[r]
                               + wi.w10 * a[r+1] + wi.w11 * bb[r+1];
                }
            } else {
                // Rare fallback: offsets too spread for the smem tile — sample global.
                const int px = x0 + lane;
#pragma unroll
                for (int r = 0; r < 4; ++r) {
                    const int py  = y0 + yb + r;
                    const int iy0 = py + wi.oy;
                    const int ix0 = px + wi.ox;
                    const bool y0ok = (unsigned)iy0       < (unsigned)H;
                    const bool y1ok = (unsigned)(iy0 + 1) < (unsigned)H;
                    const bool x0ok = (unsigned)ix0       < (unsigned)W;
                    const bool x1ok = (unsigned)(ix0 + 1) < (unsigned)W;
                    const float v00 = (y0ok && x0ok) ? __ldg(&img[iy0 * W + ix0])           : 0.f;
                    const float v01 = (y0ok && x1ok) ? __ldg(&img[iy0 * W + ix0 + 1])       : 0.f;
                    const float v10 = (y1ok && x0ok) ? __ldg(&img[(iy0 + 1) * W + ix0])     : 0.f;
                    const float v11 = (y1ok && x1ok) ? __ldg(&img[(iy0 + 1) * W + ix0 + 1]) : 0.f;
                    acc[k][r] += wi.w00 * v00 + wi.w01 * v01 + wi.w10 * v10 + wi.w11 * v11;
                }
            }
        }
    }

    // --- Write partials ---
    float* gp = g_part + (size_t)chunk * (NB * NK * HO * WO)
                       + (size_t)b * (NK * HO * WO);
#pragma unroll
    for (int k = 0; k < NK; ++k) {
#pragma unroll
        for (int r = 0; r < 4; ++r) {
            gp[(size_t)k * (HO * WO) + (y0 + yb + r) * WO + x0 + lane] = acc[k][r];
        }
    }
}

// ---------------------------------------------------------------------------
// Pass 2: 15x15 PSF convolution, 64x32 tile, 4x2 outputs/thread, f32x2 FMA.
// ---------------------------------------------------------------------------
#define P2TX 64
#define P2TY 32
#define P2RC 78      // region cols: 64 + 14
#define P2RR 46      // region rows: 32 + 14
#define P2S  80      // smem stride (float4-aligned)

__global__ void __launch_bounds__(256)
psf_conv_kernel(const float* __restrict__ psf, float* __restrict__ out)
{
    __shared__ float s_acc[P2RR * P2S];        // 14.7 KB
    __shared__ ull   s_psf2[KS * KS];          // broadcast-packed PSF, 1.8 KB

    const int tid = threadIdx.x;
    const int p   = blockIdx.z;                // plane: b*4+k
    const int x0  = blockIdx.x * P2TX;
    const int y0  = blockIdx.y * P2TY;

    if (tid < KS * KS) {
        const float w = __ldg(&psf[tid]);
        s_psf2[tid] = pack2(w, w);
    }

    const float* p0 = g_part + (size_t)p * (HO * WO);
    const float* p1 = p0 + (size_t)(NB * NK) * (HO * WO);

    // Load region: cols 0..63
    {
        const int c  = tid & 63;
        const int gx = x0 + c - KR;
        const bool xok = (unsigned)gx < (unsigned)WO;
#pragma unroll 4
        for (int r = tid >> 6; r < P2RR; r += 4) {
            const int gy = y0 + r - KR;
            float v = 0.f;
            if (xok && (unsigned)gy < (unsigned)HO) {
                const int idx = gy * WO + gx;
                v = __ldg(&p0[idx]) + __ldg(&p1[idx]);
            }
            s_acc[r * P2S + c] = v;
        }
    }
    // Load region: cols 64..77
    {
        const int c  = 64 + (tid & 15);
        const int gx = x0 + c - KR;
        const bool cok = c < P2RC;
        const bool xok = cok && (unsigned)gx < (unsigned)WO;
#pragma unroll
        for (int r = tid >> 4; r < P2RR; r += 16) {
            const int gy = y0 + r - KR;
            float v = 0.f;
            if (xok && (unsigned)gy < (unsigned)HO) {
                const int idx = gy * WO + gx;
                v = __ldg(&p0[idx]) + __ldg(&p1[idx]);
            }
            if (cok) s_acc[r * P2S + c] = v;
        }
    }
    __syncthreads();

    const int tx = (tid & 15) * 4;   // 0..60
    const int ty = (tid >> 4) * 2;   // 0..30

    ull acc00 = 0, acc01 = 0, acc10 = 0, acc11 = 0;
    ull pp[17];

    // load a region row (float4 LDS) and build overlapping f32x2 pairs
    auto load_pack = [&](int v) {
        float row[20];
        const float4* rp = reinterpret_cast<const float4*>(&s_acc[(ty + v) * P2S + tx]);
#pragma unroll
        for (int q = 0; q < 5; ++q) {
            const float4 t = rp[q];
            row[4*q+0] = t.x; row[4*q+1] = t.y; row[4*q+2] = t.z; row[4*q+3] = t.w;
        }
#pragma unroll
        for (int j = 0; j < 17; ++j) pp[j] = pack2(row[j], row[j+1]);
    };

    // v = 0: contributes only to output row 0 (ky = 0)
    load_pack(0);
#pragma unroll
    for (int kx = 0; kx < KS; ++kx) {
        const ull w = s_psf2[kx];
        fma2(acc00, w, pp[kx]);
        fma2(acc01, w, pp[kx + 2]);
    }
    // v = 1..14: contributes to both output rows
#pragma unroll 2
    for (int v = 1; v < KS; ++v) {
        load_pack(v);
#pragma unroll
        for (int kx = 0; kx < KS; ++kx) {
            const ull w0 = s_psf2[v * KS + kx];         // row 0, ky = v
            fma2(acc00, w0, pp[kx]);
            fma2(acc01, w0, pp[kx + 2]);
            const ull w1 = s_psf2[(v - 1) * KS + kx];   // row 1, ky = v-1
            fma2(acc10, w1, pp[kx]);
            fma2(acc11, w1, pp[kx + 2]);
        }
    }
    // v = 15: contributes only to output row 1 (ky = 14)
    load_pack(KS);
#pragma unroll
    for (int kx = 0; kx < KS; ++kx) {
        const ull w = s_psf2[(KS - 1) * KS + kx];
        fma2(acc10, w, pp[kx]);
        fma2(acc11, w, pp[kx + 2]);
    }

    // Store (pairs never straddle the row edge; x even, WO even)
    float* op = out + (size_t)p * (HO * WO);
    const int ybase = y0 + ty;
    const int xbase = x0 + tx;
    float lo, hi;
    if (xbase < WO) {
        unpack2(acc00, lo, hi);
        *reinterpret_cast<float2*>(&op[ybase * WO + xbase]) = make_float2(lo, hi);
        unpack2(acc10, lo, hi);
        *reinterpret_cast<float2*>(&op[(ybase + 1) * WO + xbase]) = make_float2(lo, hi);
    }
    if (xbase + 2 < WO) {
        unpack2(acc01, lo, hi);
        *reinterpret_cast<float2*>(&op[ybase * WO + xbase + 2]) = make_float2(lo, hi);
        unpack2(acc11, lo, hi);
        *reinterpret_cast<float2*>(&op[(ybase + 1) * WO + xbase + 2]) = make_float2(lo, hi);
    }
}

// ---------------------------------------------------------------------------
extern "C" void kernel_launch(void* const* d_in, const int* in_sizes, int n_in,
                              void* d_out, int out_size)
{
    const float* cube = (const float*)d_in[0];   // (4, 96, 256, 256)
    const float* dx   = (const float*)d_in[1];   // (4, 96)
    const float* dy   = (const float*)d_in[2];   // (4, 96)
    const float* psf  = (const float*)d_in[3];   // (15, 15)
    float* out        = (float*)d_out;           // (4, 4, 288, 288)

    dim3 g1(WO / TILE, HO / TILE, NB * NCHUNK);          // 9 x 9 x 8
    shift_acc_kernel<<<g1, 256>>>(cube, dx, dy);

    dim3 g2((WO + P2TX - 1) / P2TX, HO / P2TY, NB * NK); // 5 x 9 x 16
    psf_conv_kernel<<<g2, 256>>>(psf, out);
}

// round 3
// speedup vs baseline: 1.6371x; 1.0275x over previous
#include <cuda_runtime.h>
#include <cstdint>

#define PAD 16
#define H 256
#define W 256
#define HO 288
#define WO 288
#define NLAM 96
#define NB 4
#define NK 4
#define NCHUNK 2
#define LCHUNK (NLAM / NCHUNK)   // 48
#define TILE 32
#define REGROWS 64
#define RSTRIDE 66               // even -> b64-aligned pair loads

#define KS 15
#define KR 7

// Partial accumulators: [chunk][b*4+k][HO][WO]  (10.6 MB)
__device__ float g_part[NCHUNK * NB * NK * HO * WO];

typedef unsigned long long ull;

__device__ __forceinline__ ull pack2(float lo, float hi) {
    ull r;
    asm("mov.b64 %0, {%1, %2};" : "=l"(r) : "f"(lo), "f"(hi));
    return r;
}
__device__ __forceinline__ void fma2(ull& d, ull a, ull b) {
    asm("fma.rn.f32x2 %0, %1, %2, %3;" : "=l"(d) : "l"(a), "l"(b), "l"(d));
}
__device__ __forceinline__ void unpack2(ull v, float& lo, float& hi) {
    asm("mov.b64 {%0, %1}, %2;" : "=f"(lo), "=f"(hi) : "l"(v));
}
__device__ __forceinline__ void cp4(uint32_t dst, const float* src, int sz) {
    asm volatile("cp.async.ca.shared.global [%0], [%1], 4, %2;"
                 :: "r"(dst), "l"(src), "r"(sz));
}
__device__ __forceinline__ void cp_commit() {
    asm volatile("cp.async.commit_group;");
}
__device__ __forceinline__ void cp_wait0() {
    asm volatile("cp.async.wait_group 0;");
}

struct __align__(16) WPack { ull w00, w01, w10, w11; };

// ---------------------------------------------------------------------------
// Pass 1: bilinear shift-accumulate over lambda for all 4 k-sequences.
// 2x2 outputs per thread per k, f32x2 FMA, cp.async double-buffered fill.
// ---------------------------------------------------------------------------
__global__ void __launch_bounds__(256)
shift_acc_kernel(const float* __restrict__ cube,
                 const float* __restrict__ dxv,
                 const float* __restrict__ dyv)
{
    __shared__ float s_img[2][REGROWS * RSTRIDE];       // 2 x 16.5 KB
    __shared__ WPack s_wt[LCHUNK * NK];                 // 6 KB (f32x2-packed weights)
    __shared__ int2  s_off[LCHUNK * NK];                // 1.5 KB
    __shared__ short s_oymin[LCHUNK], s_oxmin[LCHUNK], s_rn[LCHUNK];
    __shared__ unsigned char s_okf[LCHUNK], s_fastf[LCHUNK];

    const int tid   = threadIdx.x;
    const int bz    = blockIdx.z;           // b * NCHUNK + chunk
    const int b     = bz >> 1;
    const int chunk = bz & 1;
    const int lam0  = chunk * LCHUNK;
    const int x0    = blockIdx.x * TILE;
    const int y0    = blockIdx.y * TILE;

    // --- Per-(lambda,k) integer offsets + f32x2-packed bilinear weights ---
    for (int i = tid; i < LCHUNK * NK; i += 256) {
        const int l   = i >> 2;
        const int k   = i & 3;
        const int lam = lam0 + l;
        const float sx = -dxv[k * NLAM + lam] - (float)PAD;
        const float sy = -dyv[k * NLAM + lam] - (float)PAD;
        const float fox = floorf(sx), foy = floorf(sy);
        const float fx = sx - fox, fy = sy - foy;
        s_off[i] = make_int2((int)fox, (int)foy);
        const float gxw = 1.f - fx, gyw = 1.f - fy;
        WPack wp;
        wp.w00 = pack2(gyw * gxw, gyw * gxw);
        wp.w01 = pack2(gyw * fx,  gyw * fx);
        wp.w10 = pack2(fy * gxw,  fy * gxw);
        wp.w11 = pack2(fy * fx,   fy * fx);
        s_wt[i] = wp;
    }
    __syncthreads();

    // --- Per-lambda union bounding box over the 4 k offsets ---
    for (int l = tid; l < LCHUNK; l += 256) {
        int oymin = s_off[l * 4].y, oymax = oymin;
        int oxmin = s_off[l * 4].x, oxmax = oxmin;
#pragma unroll
        for (int k = 1; k < NK; ++k) {
            const int oy = s_off[l * 4 + k].y;
            const int ox = s_off[l * 4 + k].x;
            oymin = min(oymin, oy); oymax = max(oymax, oy);
            oxmin = min(oxmin, ox); oxmax = max(oxmax, ox);
        }
        const int rn = TILE + 1 + (oymax - oymin);
        const int cn = TILE + 1 + (oxmax - oxmin);
        s_oymin[l] = (short)oymin;
        s_oxmin[l] = (short)oxmin;
        s_rn[l]    = (short)rn;
        const bool ok = (rn <= REGROWS && cn <= REGROWS);
        s_okf[l]   = ok ? 1 : 0;
        const int gy0 = y0 + oymin, gx0 = x0 + oxmin;
        s_fastf[l] = (ok && gy0 >= 0 && gy0 + rn <= H && gx0 >= 0 && gx0 + 64 <= W) ? 1 : 0;
    }
    __syncthreads();

    const int tx = tid & 15;     // 2-col group
    const int ty = tid >> 4;     // 2-row group
    const int fc  = tid & 63;    // fill col
    const int fr0 = tid >> 6;    // fill row start

    ull acc[NK][2];
#pragma unroll
    for (int k = 0; k < NK; ++k) { acc[k][0] = 0; acc[k][1] = 0; }

    const float* imgb = cube + (size_t)(b * NLAM + lam0) * (H * W);
    const uint32_t sb0 = (uint32_t)__cvta_generic_to_shared(&s_img[0][0]);
    const uint32_t sb1 = (uint32_t)__cvta_generic_to_shared(&s_img[1][0]);
    const ull one2 = pack2(1.f, 1.f);

    // fill lambda lf into buffer buf (cp.async, zero-fill OOB)
    auto issue_fill = [&](int lf, uint32_t sbase) {
        const float* img = imgb + (size_t)lf * (H * W);
        const int rn  = s_rn[lf];
        const int gy0 = y0 + s_oymin[lf];
        const int gx0 = x0 + s_oxmin[lf];
        uint32_t dst = sbase + (uint32_t)(fr0 * RSTRIDE + fc) * 4;
        if (s_fastf[lf]) {
            const float* src = img + (size_t)(gy0 + fr0) * W + gx0 + fc;
            for (int r = fr0; r < rn; r += 4) {
                cp4(dst, src, 4);
                src += 4 * W;
                dst += 4 * RSTRIDE * 4;
            }
        } else {
            const int gx  = gx0 + fc;
            const bool xok = (unsigned)gx < (unsigned)W;
            const int gxc = min(max(gx, 0), W - 1);
            for (int r = fr0; r < rn; r += 4) {
                const int gy = gy0 + r;
                const bool v = xok && ((unsigned)gy < (unsigned)H);
                const int gyc = min(max(gy, 0), H - 1);
                cp4(dst, img + (size_t)gyc * W + gxc, v ? 4 : 0);
                dst += 4 * RSTRIDE * 4;
            }
        }
    };

    if (s_okf[0]) issue_fill(0, sb0);
    cp_commit();

    for (int l = 0; l < LCHUNK; ++l) {
        cp_wait0();
        __syncthreads();   // fill(l) visible to all; buf[(l+1)&1] free

        if (l + 1 < LCHUNK) {
            if (s_okf[l + 1]) issue_fill(l + 1, (l + 1) & 1 ? sb1 : sb0);
            cp_commit();
        }

        const float* buf = s_img[l & 1];
        const int oym = s_oymin[l];
        const int oxm = s_oxmin[l];

        if (s_okf[l]) {
#pragma unroll
            for (int k = 0; k < NK; ++k) {
                const int2 off = s_off[l * 4 + k];
                const int obase = off.x - oxm + 2 * tx;
                const int rbase = 2 * ty + off.y - oym;
                const float* bp = buf + rbase * RSTRIDE + obase;
                ull p01[3], p12[3];
                if ((obase & 1) == 0) {
#pragma unroll
                    for (int r = 0; r < 3; ++r) {
                        const ull u = *reinterpret_cast<const ull*>(bp + r * RSTRIDE);
                        const float v2s = bp[r * RSTRIDE + 2];
                        float lo_, hi_; unpack2(u, lo_, hi_);
                        p01[r] = u;
                        p12[r] = pack2(hi_, v2s);
                    }
                } else {
#pragma unroll
                    for (int r = 0; r < 3; ++r) {
                        const float v0 = bp[r * RSTRIDE];
                        const ull u = *reinterpret_cast<const ull*>(bp + r * RSTRIDE + 1);
                        float lo_, hi_; unpack2(u, lo_, hi_);
                        p01[r] = pack2(v0, lo_);
                        p12[r] = u;
                    }
                }
                const WPack wp = s_wt[l * 4 + k];
                fma2(acc[k][0], wp.w00, p01[0]);
                fma2(acc[k][0], wp.w01, p12[0]);
                fma2(acc[k][0], wp.w10, p01[1]);
                fma2(acc[k][0], wp.w11, p12[1]);
                fma2(acc[k][1], wp.w00, p01[1]);
                fma2(acc[k][1], wp.w01, p12[1]);
                fma2(acc[k][1], wp.w10, p01[2]);
                fma2(acc[k][1], wp.w11, p12[2]);
            }
        } else {
            // Rare fallback: offsets too spread for the smem tile — sample global.
            const float* img = imgb + (size_t)l * (H * W);
#pragma unroll
            for (int k = 0; k < NK; ++k) {
                const int2 off = s_off[l * 4 + k];
                float w00, w01, w10, w11, d0;
                unpack2(s_wt[l * 4 + k].w00, w00, d0);
                unpack2(s_wt[l * 4 + k].w01, w01, d0);
                unpack2(s_wt[l * 4 + k].w10, w10, d0);
                unpack2(s_wt[l * 4 + k].w11, w11, d0);
#pragma unroll
                for (int r = 0; r < 2; ++r) {
                    float s[2];
#pragma unroll
                    for (int c = 0; c < 2; ++c) {
                        const int iy0 = y0 + 2 * ty + r + off.y;
                        const int ix0 = x0 + 2 * tx + c + off.x;
                        const bool y0ok = (unsigned)iy0       < (unsigned)H;
                        const bool y1ok = (unsigned)(iy0 + 1) < (unsigned)H;
                        const bool x0ok = (unsigned)ix0       < (unsigned)W;
                        const bool x1ok = (unsigned)(ix0 + 1) < (unsigned)W;
                        const float v00 = (y0ok && x0ok) ? __ldg(&img[iy0 * W + ix0])           : 0.f;
                        const float v01 = (y0ok && x1ok) ? __ldg(&img[iy0 * W + ix0 + 1])       : 0.f;
                        const float v10 = (y1ok && x0ok) ? __ldg(&img[(iy0 + 1) * W + ix0])     : 0.f;
                        const float v11 = (y1ok && x1ok) ? __ldg(&img[(iy0 + 1) * W + ix0 + 1]) : 0.f;
                        s[c] = w00 * v00 + w01 * v01 + w10 * v10 + w11 * v11;
                    }
                    fma2(acc[k][r], one2, pack2(s[0], s[1]));
                }
            }
        }
    }

    // --- Write partials (float2 stores, 2 rows x 2 cols per k) ---
    float* gp = g_part + (size_t)chunk * (NB * NK * HO * WO)
                       + (size_t)b * (NK * HO * WO);
#pragma unroll
    for (int k = 0; k < NK; ++k) {
#pragma unroll
        for (int r = 0; r < 2; ++r) {
            float lo, hi;
            unpack2(acc[k][r], lo, hi);
            *reinterpret_cast<float2*>(
                &gp[(size_t)k * (HO * WO) + (y0 + 2 * ty + r) * WO + x0 + 2 * tx]) =
                make_float2(lo, hi);
        }
    }
}

// ---------------------------------------------------------------------------
// Pass 2: 15x15 PSF conv, 64x64 tile, 4x4 outputs/thread, f32x2 FMA.
// ---------------------------------------------------------------------------
#define C2T  64
#define C2RR 78
#define C2RC 78
#define C2RS 80

__global__ void __launch_bounds__(256)
psf_conv_kernel(const float* __restrict__ psf, float* __restrict__ out)
{
    __shared__ float s_a[C2RR * C2RS];     // 24.96 KB
    __shared__ ull   s_psf2[KS * KS];      // 1.8 KB

    const int tid = threadIdx.x;
    const int p   = blockIdx.z;            // plane: b*4+k
    const int x0  = blockIdx.x * C2T;
    const int y0  = blockIdx.y * C2T;

    if (tid < KS * KS) {
        const float w = __ldg(&psf[tid]);
        s_psf2[tid] = pack2(w, w);
    }

    const float* p0 = g_part + (size_t)p * (HO * WO);
    const float* p1 = p0 + (size_t)(NB * NK) * (HO * WO);

    for (int i = tid; i < C2RR * C2RS; i += 256) {
        const int r = i / C2RS;
        const int c = i - r * C2RS;
        const int gy = y0 + r - KR;
        const int gx = x0 + c - KR;
        float v = 0.f;
        if (c < C2RC && (unsigned)gy < (unsigned)HO && (unsigned)gx < (unsigned)WO) {
            const int idx = gy * WO + gx;
            v = __ldg(&p0[idx]) + __ldg(&p1[idx]);
        }
        s_a[i] = v;
    }
    __syncthreads();

    const int tx   = tid & 15;
    const int ty   = tid >> 4;
    const int col4 = tx * 4;
    const int row4 = ty * 4;

    ull A[4][2];
#pragma unroll
    for (int r = 0; r < 4; ++r) { A[r][0] = 0; A[r][1] = 0; }

    // Load 18 floats of region row v, build 17 overlapping f32x2 pairs.
    auto loadrow = [&](int v, ull* pp) {
        const float* rb = &s_a[(row4 + v) * C2RS + col4];
        float f[18];
#pragma unroll
        for (int q = 0; q < 4; ++q) {
            const float4 t = reinterpret_cast<const float4*>(rb)[q];
            f[4*q+0] = t.x; f[4*q+1] = t.y; f[4*q+2] = t.z; f[4*q+3] = t.w;
        }
        const float2 t2 = *reinterpret_cast<const float2*>(rb + 16);
        f[16] = t2.x; f[17] = t2.y;
#pragma unroll
        for (int j = 0; j < 17; ++j) pp[j] = pack2(f[j], f[j + 1]);
    };

    auto dorow = [&](ull* Ar, const ull* pp, int ky) {
        const ull* wrow = &s_psf2[ky * KS];
#pragma unroll
        for (int kx = 0; kx < KS; ++kx) {
            const ull w = wrow[kx];
            fma2(Ar[0], w, pp[kx]);
            fma2(Ar[1], w, pp[kx + 2]);
        }
    };

    {   ull pp[17]; loadrow(0, pp); dorow(A[0], pp, 0); }
    {   ull pp[17]; loadrow(1, pp); dorow(A[0], pp, 1); dorow(A[1], pp, 0); }
    {   ull pp[17]; loadrow(2, pp); dorow(A[0], pp, 2); dorow(A[1], pp, 1);
        dorow(A[2], pp, 0); }
#pragma unroll 2
    for (int v = 3; v < KS; ++v) {
        ull pp[17]; loadrow(v, pp);
        dorow(A[0], pp, v);
        dorow(A[1], pp, v - 1);
        dorow(A[2], pp, v - 2);
        dorow(A[3], pp, v - 3);
    }
    {   ull pp[17]; loadrow(15, pp); dorow(A[1], pp, 14); dorow(A[2], pp, 13);
        dorow(A[3], pp, 12); }
    {   ull pp[17]; loadrow(16, pp); dorow(A[2], pp, 14); dorow(A[3], pp, 13); }
    {   ull pp[17]; loadrow(17, pp); dorow(A[3], pp, 14); }

    float* op = out + (size_t)p * (HO * WO);
    const int xo = x0 + col4;
    if (xo < WO) {
#pragma unroll
        for (int r = 0; r < 4; ++r) {
            const int yo = y0 + row4 + r;
            if (yo < HO) {
                float lo, hi;
                unpack2(A[r][0], lo, hi);
                *reinterpret_cast<float2*>(&op[yo * WO + xo]) = make_float2(lo, hi);
                unpack2(A[r][1], lo, hi);
                *reinterpret_cast<float2*>(&op[yo * WO + xo + 2]) = make_float2(lo, hi);
            }
        }
    }
}

// ---------------------------------------------------------------------------
extern "C" void kernel_launch(void* const* d_in, const int* in_sizes, int n_in,
                              void* d_out, int out_size)
{
    const float* cube = (const float*)d_in[0];   // (4, 96, 256, 256)
    const float* dx   = (const float*)d_in[1];   // (4, 96)
    const float* dy   = (const float*)d_in[2];   // (4, 96)
    const float* psf  = (const float*)d_in[3];   // (15, 15)
    float* out        = (float*)d_out;           // (4, 4, 288, 288)

    dim3 g1(WO / TILE, HO / TILE, NB * NCHUNK);            // 9 x 9 x 8
    shift_acc_kernel<<<g1, 256>>>(cube, dx, dy);

    dim3 g2((WO + C2T - 1) / C2T, (HO + C2T - 1) / C2T, NB * NK);  // 5 x 5 x 16
    psf_conv_kernel<<<g2, 256>>>(psf, out);
}

// round 5
// speedup vs baseline: 1.9131x; 1.1686x over previous
#include <cuda_runtime.h>
#include <cstdint>

#define PAD 16
#define H 256
#define W 256
#define HO 288
#define WO 288
#define NLAM 96
#define NB 4
#define NK 4
#define NCHUNK 4
#define LCHUNK (NLAM / NCHUNK)   // 24
#define TILE 32
#define REGROWS 56
#define REGCOLS 56
#define RSTRIDE 58               // even -> b64-aligned pair loads
#define NSTAGE 3

#define KS 15
#define KR 7

// Partial accumulators: [chunk][b*4+k][HO][WO]  (4 * 16 * 288*288 * 4B = 21.2 MB)
__device__ float g_part[NCHUNK * NB * NK * HO * WO];

typedef unsigned long long ull;

__device__ __forceinline__ ull pack2(float lo, float hi) {
    ull r;
    asm("mov.b64 %0, {%1, %2};" : "=l"(r) : "f"(lo), "f"(hi));
    return r;
}
__device__ __forceinline__ void fma2(ull& d, ull a, ull b) {
    asm("fma.rn.f32x2 %0, %1, %2, %3;" : "=l"(d) : "l"(a), "l"(b), "l"(d));
}
__device__ __forceinline__ void unpack2(ull v, float& lo, float& hi) {
    asm("mov.b64 {%0, %1}, %2;" : "=f"(lo), "=f"(hi) : "l"(v));
}
__device__ __forceinline__ void cp4(uint32_t dst, const float* src, int sz) {
    asm volatile("cp.async.ca.shared.global [%0], [%1], 4, %2;"
                 :: "r"(dst), "l"(src), "r"(sz));
}
__device__ __forceinline__ void cp_commit() {
    asm volatile("cp.async.commit_group;");
}
__device__ __forceinline__ void cp_wait1() {
    asm volatile("cp.async.wait_group 1;");
}
__device__ __forceinline__ void cp_wait0() {
    asm volatile("cp.async.wait_group 0;");
}

struct __align__(16) WPack { ull w00, w01, w10, w11; };

// ---------------------------------------------------------------------------
// Pass 1: bilinear shift-accumulate over a lambda chunk for all 4 k-sequences.
// 2x2 outputs per thread per k, f32x2 FMA, depth-3 cp.async pipeline.
// ---------------------------------------------------------------------------
__global__ void __launch_bounds__(256)
shift_acc_kernel(const float* __restrict__ cube,
                 const float* __restrict__ dxv,
                 const float* __restrict__ dyv)
{
    __shared__ float s_img[NSTAGE][REGROWS * RSTRIDE];  // 3 x 13 KB
    __shared__ WPack s_wt[LCHUNK * NK];                 // 3 KB
    __shared__ int2  s_off[LCHUNK * NK];                // 768 B
    __shared__ short s_oymin[LCHUNK], s_oxmin[LCHUNK], s_rn[LCHUNK];
    __shared__ unsigned char s_okf[LCHUNK], s_fastf[LCHUNK];

    const int tid   = threadIdx.x;
    const int bz    = blockIdx.z;            // b * NCHUNK + chunk
    const int b     = bz >> 2;
    const int chunk = bz & 3;
    const int lam0  = chunk * LCHUNK;
    const int x0    = blockIdx.x * TILE;
    const int y0    = blockIdx.y * TILE;

    // --- Per-(lambda,k) integer offsets + f32x2-packed bilinear weights ---
    for (int i = tid; i < LCHUNK * NK; i += 256) {
        const int l   = i >> 2;
        const int k   = i & 3;
        const int lam = lam0 + l;
        const float sx = -dxv[k * NLAM + lam] - (float)PAD;
        const float sy = -dyv[k * NLAM + lam] - (float)PAD;
        const float fox = floorf(sx), foy = floorf(sy);
        const float fx = sx - fox, fy = sy - foy;
        s_off[i] = make_int2((int)fox, (int)foy);
        const float gxw = 1.f - fx, gyw = 1.f - fy;
        WPack wp;
        wp.w00 = pack2(gyw * gxw, gyw * gxw);
        wp.w01 = pack2(gyw * fx,  gyw * fx);
        wp.w10 = pack2(fy * gxw,  fy * gxw);
        wp.w11 = pack2(fy * fx,   fy * fx);
        s_wt[i] = wp;
    }
    __syncthreads();

    // --- Per-lambda union bounding box over the 4 k offsets ---
    for (int l = tid; l < LCHUNK; l += 256) {
        int oymin = s_off[l * 4].y, oymax = oymin;
        int oxmin = s_off[l * 4].x, oxmax = oxmin;
#pragma unroll
        for (int k = 1; k < NK; ++k) {
            const int oy = s_off[l * 4 + k].y;
            const int ox = s_off[l * 4 + k].x;
            oymin = min(oymin, oy); oymax = max(oymax, oy);
            oxmin = min(oxmin, ox); oxmax = max(oxmax, ox);
        }
        const int rn = TILE + 1 + (oymax - oymin);
        const int cn = TILE + 1 + (oxmax - oxmin);
        s_oymin[l] = (short)oymin;
        s_oxmin[l] = (short)oxmin;
        s_rn[l]    = (short)rn;
        const bool ok = (rn <= REGROWS && cn <= REGCOLS);
        s_okf[l]   = ok ? 1 : 0;
        const int gy0 = y0 + oymin, gx0 = x0 + oxmin;
        s_fastf[l] = (ok && gy0 >= 0 && gy0 + rn <= H &&
                      gx0 >= 0 && gx0 + REGCOLS <= W) ? 1 : 0;
    }
    __syncthreads();

    const int tx  = tid & 15;    // 2-col group
    const int ty  = tid >> 4;    // 2-row group
    const int fc  = tid & 63;    // fill col (active if < REGCOLS)
    const int fr0 = tid >> 6;    // fill row start

    ull acc[NK][2];
#pragma unroll
    for (int k = 0; k < NK; ++k) { acc[k][0] = 0; acc[k][1] = 0; }

    const float* imgb = cube + (size_t)(b * NLAM + lam0) * (H * W);
    const uint32_t sbase0 = (uint32_t)__cvta_generic_to_shared(&s_img[0][0]);
    const ull one2 = pack2(1.f, 1.f);

    auto issue_fill = [&](int lf, int stage) {
        if (fc >= REGCOLS) return;
        const float* img = imgb + (size_t)lf * (H * W);
        const int rn  = s_rn[lf];
        const int gy0 = y0 + s_oymin[lf];
        const int gx0 = x0 + s_oxmin[lf];
        uint32_t dst = sbase0 + (uint32_t)(stage * REGROWS * RSTRIDE + fr0 * RSTRIDE + fc) * 4;
        if (s_fastf[lf]) {
            const float* src = img + (size_t)(gy0 + fr0) * W + gx0 + fc;
            for (int r = fr0; r < rn; r += 4) {
                cp4(dst, src, 4);
                src += 4 * W;
                dst += 4 * RSTRIDE * 4;
            }
        } else {
            const int gx  = gx0 + fc;
            const bool xok = (unsigned)gx < (unsigned)W;
            const int gxc = min(max(gx, 0), W - 1);
            for (int r = fr0; r < rn; r += 4) {
                const int gy = gy0 + r;
                const bool v = xok && ((unsigned)gy < (unsigned)H);
                const int gyc = min(max(gy, 0), H - 1);
                cp4(dst, img + (size_t)gyc * W + gxc, v ? 4 : 0);
                dst += 4 * RSTRIDE * 4;
            }
        }
    };

    // Prologue: prefetch lambda 0 and 1.
    if (s_okf[0]) issue_fill(0, 0);
    cp_commit();
    if (LCHUNK > 1) {
        if (s_okf[1]) issue_fill(1, 1);
        cp_commit();
    }

    int stage = 0;
    for (int l = 0; l < LCHUNK; ++l) {
        // Retire fill(l). NOTE: on the final iteration only ONE group remains
        // pending, so wait_group 1 would NOT guarantee fill(l) completed —
        // must drain fully there (this was the R4 correctness bug).
        if (l == LCHUNK - 1) cp_wait0(); else cp_wait1();
        __syncthreads();   // all threads see fill(l); compute(l-1) done

        if (l + 2 < LCHUNK) {
            int st2 = stage + 2; if (st2 >= NSTAGE) st2 -= NSTAGE;
            if (s_okf[l + 2]) issue_fill(l + 2, st2);
            cp_commit();
        }

        const float* buf = s_img[stage];
        const int oym = s_oymin[l];
        const int oxm = s_oxmin[l];

        if (s_okf[l]) {
#pragma unroll
            for (int k = 0; k < NK; ++k) {
                const int2 off = s_off[l * 4 + k];
                const int obase = off.x - oxm + 2 * tx;
                const int rbase = 2 * ty + off.y - oym;
                const float* bp = buf + rbase * RSTRIDE + obase;
                ull p01[3], p12[3];
                if ((obase & 1) == 0) {
#pragma unroll
                    for (int r = 0; r < 3; ++r) {
                        const ull u = *reinterpret_cast<const ull*>(bp + r * RSTRIDE);
                        const float v2s = bp[r * RSTRIDE + 2];
                        float lo_, hi_; unpack2(u, lo_, hi_);
                        p01[r] = u;
                        p12[r] = pack2(hi_, v2s);
                    }
                } else {
#pragma unroll
                    for (int r = 0; r < 3; ++r) {
                        const float v0 = bp[r * RSTRIDE];
                        const ull u = *reinterpret_cast<const ull*>(bp + r * RSTRIDE + 1);
                        float lo_, hi_; unpack2(u, lo_, hi_);
                        p01[r] = pack2(v0, lo_);
                        p12[r] = u;
                    }
                }
                const WPack wp = s_wt[l * 4 + k];
                fma2(acc[k][0], wp.w00, p01[0]);
                fma2(acc[k][0], wp.w01, p12[0]);
                fma2(acc[k][0], wp.w10, p01[1]);
                fma2(acc[k][0], wp.w11, p12[1]);
                fma2(acc[k][1], wp.w00, p01[1]);
                fma2(acc[k][1], wp.w01, p12[1]);
                fma2(acc[k][1], wp.w10, p01[2]);
                fma2(acc[k][1], wp.w11, p12[2]);
            }
        } else {
            // Rare fallback: offsets too spread for the smem tile — sample global.
            const float* img = imgb + (size_t)l * (H * W);
#pragma unroll
            for (int k = 0; k < NK; ++k) {
                const int2 off = s_off[l * 4 + k];
                float w00, w01, w10, w11, d0;
                unpack2(s_wt[l * 4 + k].w00, w00, d0);
                unpack2(s_wt[l * 4 + k].w01, w01, d0);
                unpack2(s_wt[l * 4 + k].w10, w10, d0);
                unpack2(s_wt[l * 4 + k].w11, w11, d0);
#pragma unroll
                for (int r = 0; r < 2; ++r) {
                    float s[2];
#pragma unroll
                    for (int c = 0; c < 2; ++c) {
                        const int iy0 = y0 + 2 * ty + r + off.y;
                        const int ix0 = x0 + 2 * tx + c + off.x;
                        const bool y0ok = (unsigned)iy0       < (unsigned)H;
                        const bool y1ok = (unsigned)(iy0 + 1) < (unsigned)H;
                        const bool x0ok = (unsigned)ix0       < (unsigned)W;
                        const bool x1ok = (unsigned)(ix0 + 1) < (unsigned)W;
                        const float v00 = (y0ok && x0ok) ? __ldg(&img[iy0 * W + ix0])           : 0.f;
                        const float v01 = (y0ok && x1ok) ? __ldg(&img[iy0 * W + ix0 + 1])       : 0.f;
                        const float v10 = (y1ok && x0ok) ? __ldg(&img[(iy0 + 1) * W + ix0])     : 0.f;
                        const float v11 = (y1ok && x1ok) ? __ldg(&img[(iy0 + 1) * W + ix0 + 1]) : 0.f;
                        s[c] = w00 * v00 + w01 * v01 + w10 * v10 + w11 * v11;
                    }
                    fma2(acc[k][r], one2, pack2(s[0], s[1]));
                }
            }
        }

        if (++stage == NSTAGE) stage = 0;
    }

    // --- Write partials (float2 stores, 2 rows x 2 cols per k) ---
    float* gp = g_part + (size_t)chunk * (NB * NK * HO * WO)
                       + (size_t)b * (NK * HO * WO);
#pragma unroll
    for (int k = 0; k < NK; ++k) {
#pragma unroll
        for (int r = 0; r < 2; ++r) {
            float lo, hi;
            unpack2(acc[k][r], lo, hi);
            *reinterpret_cast<float2*>(
                &gp[(size_t)k * (HO * WO) + (y0 + 2 * ty + r) * WO + x0 + 2 * tx]) =
                make_float2(lo, hi);
        }
    }
}

// ---------------------------------------------------------------------------
// Pass 2: 15x15 PSF conv, 64x32 tile, 4x2 outputs/thread, f32x2 FMA.
// ---------------------------------------------------------------------------
#define P2TX 64
#define P2TY 32
#define P2RC 78      // region cols: 64 + 14
#define P2RR 46      // region rows: 32 + 14
#define P2S  80      // smem stride (float4-aligned)

__global__ void __launch_bounds__(256)
psf_conv_kernel(const float* __restrict__ psf, float* __restrict__ out)
{
    __shared__ float s_acc[P2RR * P2S];        // 14.7 KB
    __shared__ ull   s_psf2[KS * KS];          // 1.8 KB

    const int tid = threadIdx.x;
    const int p   = blockIdx.z;                // plane: b*4+k
    const int x0  = blockIdx.x * P2TX;
    const int y0  = blockIdx.y * P2TY;

    if (tid < KS * KS) {
        const float w = __ldg(&psf[tid]);
        s_psf2[tid] = pack2(w, w);
    }

    const float* p0 = g_part + (size_t)p * (HO * WO);
    const size_t  pstep = (size_t)(NB * NK) * (HO * WO);

    // Load region: cols 0..63
    {
        const int c  = tid & 63;
        const int gx = x0 + c - KR;
        const bool xok = (unsigned)gx < (unsigned)WO;
#pragma unroll 4
        for (int r = tid >> 6; r < P2RR; r += 4) {
            const int gy = y0 + r - KR;
            float v = 0.f;
            if (xok && (unsigned)gy < (unsigned)HO) {
                const int idx = gy * WO + gx;
                v = __ldg(&p0[idx]) + __ldg(&p0[idx + pstep])
                  + __ldg(&p0[idx + 2 * pstep]) + __ldg(&p0[idx + 3 * pstep]);
            }
            s_acc[r * P2S + c] = v;
        }
    }
    // Load region: cols 64..77
    {
        const int c  = 64 + (tid & 15);
        const int gx = x0 + c - KR;
        const bool cok = c < P2RC;
        const bool xok = cok && (unsigned)gx < (unsigned)WO;
#pragma unroll
        for (int r = tid >> 4; r < P2RR; r += 16) {
            const int gy = y0 + r - KR;
            float v = 0.f;
            if (xok && (unsigned)gy < (unsigned)HO) {
                const int idx = gy * WO + gx;
                v = __ldg(&p0[idx]) + __ldg(&p0[idx + pstep])
                  + __ldg(&p0[idx + 2 * pstep]) + __ldg(&p0[idx + 3 * pstep]);
            }
            if (cok) s_acc[r * P2S + c] = v;
        }
    }
    __syncthreads();

    const int tx = (tid & 15) * 4;   // 0..60
    const int ty = (tid >> 4) * 2;   // 0..30

    ull acc00 = 0, acc01 = 0, acc10 = 0, acc11 = 0;
    ull pp[17];

    auto load_pack = [&](int v) {
        float row[20];
        const float4* rp = reinterpret_cast<const float4*>(&s_acc[(ty + v) * P2S + tx]);
#pragma unroll
        for (int q = 0; q < 5; ++q) {
            const float4 t = rp[q];
            row[4*q+0] = t.x; row[4*q+1] = t.y; row[4*q+2] = t.z; row[4*q+3] = t.w;
        }
#pragma unroll
        for (int j = 0; j < 17; ++j) pp[j] = pack2(row[j], row[j+1]);
    };

    // v = 0: contributes only to output row 0 (ky = 0)
    load_pack(0);
#pragma unroll
    for (int kx = 0; kx < KS; ++kx) {
        const ull w = s_psf2[kx];
        fma2(acc00, w, pp[kx]);
        fma2(acc01, w, pp[kx + 2]);
    }
    // v = 1..14: contributes to both output rows
#pragma unroll 2
    for (int v = 1; v < KS; ++v) {
        load_pack(v);
#pragma unroll
        for (int kx = 0; kx < KS; ++kx) {
            const ull w0 = s_psf2[v * KS + kx];         // row 0, ky = v
            fma2(acc00, w0, pp[kx]);
            fma2(acc01, w0, pp[kx + 2]);
            const ull w1 = s_psf2[(v - 1) * KS + kx];   // row 1, ky = v-1
            fma2(acc10, w1, pp[kx]);
            fma2(acc11, w1, pp[kx + 2]);
        }
    }
    // v = 15: contributes only to output row 1 (ky = 14)
    load_pack(KS);
#pragma unroll
    for (int kx = 0; kx < KS; ++kx) {
        const ull w = s_psf2[(KS - 1) * KS + kx];
        fma2(acc10, w, pp[kx]);
        fma2(acc11, w, pp[kx + 2]);
    }

    float* op = out + (size_t)p * (HO * WO);
    const int ybase = y0 + ty;
    const int xbase = x0 + tx;
    float lo, hi;
    if (xbase < WO) {
        unpack2(acc00, lo, hi);
        *reinterpret_cast<float2*>(&op[ybase * WO + xbase]) = make_float2(lo, hi);
        unpack2(acc10, lo, hi);
        *reinterpret_cast<float2*>(&op[(ybase + 1) * WO + xbase]) = make_float2(lo, hi);
    }
    if (xbase + 2 < WO) {
        unpack2(acc01, lo, hi);
        *reinterpret_cast<float2*>(&op[ybase * WO + xbase + 2]) = make_float2(lo, hi);
        unpack2(acc11, lo, hi);
        *reinterpret_cast<float2*>(&op[(ybase + 1) * WO + xbase + 2]) = make_float2(lo, hi);
    }
}

// ---------------------------------------------------------------------------
extern "C" void kernel_launch(void* const* d_in, const int* in_sizes, int n_in,
                              void* d_out, int out_size)
{
    const float* cube = (const float*)d_in[0];   // (4, 96, 256, 256)
    const float* dx   = (const float*)d_in[1];   // (4, 96)
    const float* dy   = (const float*)d_in[2];   // (4, 96)
    const float* psf  = (const float*)d_in[3];   // (15, 15)
    float* out        = (float*)d_out;           // (4, 4, 288, 288)

    dim3 g1(WO / TILE, HO / TILE, NB * NCHUNK);           // 9 x 9 x 16
    shift_acc_kernel<<<g1, 256>>>(cube, dx, dy);

    dim3 g2((WO + P2TX - 1) / P2TX, HO / P2TY, NB * NK);  // 5 x 9 x 16
    psf_conv_kernel<<<g2, 256>>>(psf, out);
}

// round 7
// speedup vs baseline: 2.0053x; 1.0482x over previous
#include <cuda_runtime.h>
#include <cstdint>

#define PAD 16
#define H 256
#define W 256
#define HO 288
#define WO 288
#define NLAM 96
#define NB 4
#define NK 4
#define NCHUNK 4
#define LCHUNK (NLAM / NCHUNK)   // 24
#define TILE 32
#define REGROWS 56
#define REGCOLS 64               // aligned-float4 fill width
#define RSTRIDE 68               // multiple of 4 -> 16B-aligned row bases
#define NSTAGE 4
#define STAGE_FLOATS (REGROWS * RSTRIDE)
#define SMEM_DYN (NSTAGE * STAGE_FLOATS * 4)   // 60928 B

#define KS 15
#define KR 7

// Partial accumulators: [chunk][b*4+k][HO][WO]  (21.2 MB)
__device__ float g_part[NCHUNK * NB * NK * HO * WO];

typedef unsigned long long ull;

__device__ __forceinline__ ull pack2(float lo, float hi) {
    ull r;
    asm("mov.b64 %0, {%1, %2};" : "=l"(r) : "f"(lo), "f"(hi));
    return r;
}
__device__ __forceinline__ void fma2(ull& d, ull a, ull b) {
    asm("fma.rn.f32x2 %0, %1, %2, %3;" : "=l"(d) : "l"(a), "l"(b), "l"(d));
}
__device__ __forceinline__ void unpack2(ull v, float& lo, float& hi) {
    asm("mov.b64 {%0, %1}, %2;" : "=f"(lo), "=f"(hi) : "l"(v));
}
__device__ __forceinline__ void cp4(uint32_t dst, const float* src, int sz) {
    asm volatile("cp.async.ca.shared.global [%0], [%1], 4, %2;"
                 :: "r"(dst), "l"(src), "r"(sz));
}
__device__ __forceinline__ void cp16(uint32_t dst, const float* src) {
    asm volatile("cp.async.cg.shared.global [%0], [%1], 16;"
                 :: "r"(dst), "l"(src));
}
__device__ __forceinline__ void cp_commit() {
    asm volatile("cp.async.commit_group;");
}

struct __align__(16) WPack { ull w00, w01, w10, w11; };

// ---------------------------------------------------------------------------
// Pass 1: bilinear shift-accumulate over a lambda chunk for all 4 k-sequences.
// 2x2 outputs/thread/k, f32x2 FMA, 4-stage cp.async ring (float4 fast fills).
// ---------------------------------------------------------------------------
__global__ void __launch_bounds__(256, 3)
shift_acc_kernel(const float* __restrict__ cube,
                 const float* __restrict__ dxv,
                 const float* __restrict__ dyv)
{
    extern __shared__ float s_dyn[];                    // NSTAGE stages
    __shared__ WPack s_wt[LCHUNK * NK];                 // 3 KB
    __shared__ int2  s_off[LCHUNK * NK];                // 768 B
    __shared__ short s_oymin[LCHUNK], s_oxa[LCHUNK], s_rn[LCHUNK];
    __shared__ unsigned char s_okf[LCHUNK], s_fastf[LCHUNK];

    const int tid   = threadIdx.x;
    const int bz    = blockIdx.z;            // b * NCHUNK + chunk
    const int b     = bz >> 2;
    const int chunk = bz & 3;
    const int lam0  = chunk * LCHUNK;
    const int x0    = blockIdx.x * TILE;
    const int y0    = blockIdx.y * TILE;

    // --- Per-(lambda,k) integer offsets + f32x2-packed bilinear weights ---
    for (int i = tid; i < LCHUNK * NK; i += 256) {
        const int l   = i >> 2;
        const int k   = i & 3;
        const int lam = lam0 + l;
        const float sx = -dxv[k * NLAM + lam] - (float)PAD;
        const float sy = -dyv[k * NLAM + lam] - (float)PAD;
        const float fox = floorf(sx), foy = floorf(sy);
        const float fx = sx - fox, fy = sy - foy;
        s_off[i] = make_int2((int)fox, (int)foy);
        const float gxw = 1.f - fx, gyw = 1.f - fy;
        WPack wp;
        wp.w00 = pack2(gyw * gxw, gyw * gxw);
        wp.w01 = pack2(gyw * fx,  gyw * fx);
        wp.w10 = pack2(fy * gxw,  fy * gxw);
        wp.w11 = pack2(fy * fx,   fy * fx);
        s_wt[i] = wp;
    }
    __syncthreads();

    // --- Per-lambda union bounding box over the 4 k offsets (x aligned to 4) ---
    for (int l = tid; l < LCHUNK; l += 256) {
        int oymin = s_off[l * 4].y, oymax = oymin;
        int oxmin = s_off[l * 4].x, oxmax = oxmin;
#pragma unroll
        for (int k = 1; k < NK; ++k) {
            const int oy = s_off[l * 4 + k].y;
            const int ox = s_off[l * 4 + k].x;
            oymin = min(oymin, oy); oymax = max(oymax, oy);
            oxmin = min(oxmin, ox); oxmax = max(oxmax, ox);
        }
        const int oxa = oxmin & ~3;                    // float4-aligned origin
        const int rn  = TILE + 1 + (oymax - oymin);
        const int cna = TILE + 1 + (oxmax - oxa);
        s_oymin[l] = (short)oymin;
        s_oxa[l]   = (short)oxa;
        s_rn[l]    = (short)rn;
        const bool ok = (rn <= REGROWS && cna <= REGCOLS);
        s_okf[l]   = ok ? 1 : 0;
        const int gy0 = y0 + oymin, gx0 = x0 + oxa;
        s_fastf[l] = (ok && gy0 >= 0 && gy0 + rn <= H &&
                      gx0 >= 0 && gx0 + REGCOLS <= W) ? 1 : 0;
    }
    __syncthreads();

    const int tx  = tid & 15;    // 2-col group
    const int ty  = tid >> 4;    // 2-row group

    ull acc[NK][2];
#pragma unroll
    for (int k = 0; k < NK; ++k) { acc[k][0] = 0; acc[k][1] = 0; }

    const float* imgb = cube + (size_t)(b * NLAM + lam0) * (H * W);
    const uint32_t sbase0 = (uint32_t)__cvta_generic_to_shared(&s_dyn[0]);
    const ull one2 = pack2(1.f, 1.f);

    auto issue_fill = [&](int lf, int stage) {
        const float* img = imgb + (size_t)lf * (H * W);
        const int rn  = s_rn[lf];
        const int gy0 = y0 + s_oymin[lf];
        const int gx0 = x0 + s_oxa[lf];
        const uint32_t sb = sbase0 + (uint32_t)(stage * STAGE_FLOATS) * 4;
        if (s_fastf[lf]) {
            // interior: 16B cp.async, 16 float4-columns x rn rows
            const int col4 = (tid & 15) * 4;
            const int r0   = tid >> 4;
            const float* src = img + (size_t)(gy0 + r0) * W + gx0 + col4;
            uint32_t dst = sb + (uint32_t)(r0 * RSTRIDE + col4) * 4;
#pragma unroll
            for (int r = r0; r < REGROWS; r += 16) {
                if (r < rn) cp16(dst, src);
                src += 16 * W;
                dst += 16 * RSTRIDE * 4;
            }
        } else {
            // boundary: scalar cp.async with zero-fill
            const int c   = tid & 63;
            const int r0s = tid >> 6;
            const int gx  = gx0 + c;
            const bool xok = (unsigned)gx < (unsigned)W;
            const int gxc = min(max(gx, 0), W - 1);
            uint32_t dst = sb + (uint32_t)(r0s * RSTRIDE + c) * 4;
            for (int r = r0s; r < rn; r += 4) {
                const int gy = gy0 + r;
                const bool v = xok && ((unsigned)gy < (unsigned)H);
                const int gyc = min(max(gy, 0), H - 1);
                cp4(dst, img + (size_t)gyc * W + gxc, v ? 4 : 0);
                dst += 4 * RSTRIDE * 4;
            }
        }
    };

    // Prologue: prefetch lambda 0 and 1.
    if (s_okf[0]) issue_fill(0, 0);
    cp_commit();
    if (s_okf[1]) issue_fill(1, 1);
    cp_commit();

    for (int l = 0; l < LCHUNK; ++l) {
        // Issue fill(l+2) BEFORE waiting: it targets stage (l+2)&3 == (l-2)&3,
        // whose compute finished at sync(l-1) for all warps -> race-free.
        if (l + 2 < LCHUNK) {
            if (s_okf[l + 2]) issue_fill(l + 2, (l + 2) & 3);
            cp_commit();
        }
        // Retire fill(l): pending groups are l..min(l+2,LCHUNK-1).
        const int rem = LCHUNK - 1 - l;
        if (rem >= 2)      asm volatile("cp.async.wait_group 2;");
        else if (rem == 1) asm volatile("cp.async.wait_group 1;");
        else               asm volatile("cp.async.wait_group 0;");
        __syncthreads();   // all threads' fill(l) visible; compute(l-1) done

        const float* buf = s_dyn + (l & 3) * STAGE_FLOATS;
        const int oym = s_oymin[l];
        const int oxa = s_oxa[l];

        if (s_okf[l]) {
#pragma unroll
            for (int k = 0; k < NK; ++k) {
                const int2 off = s_off[l * 4 + k];
                const int obase = off.x - oxa + 2 * tx;
                const int rbase = 2 * ty + off.y - oym;
                const float* bp = buf + rbase * RSTRIDE + obase;
                ull p01[3], p12[3];
                if ((obase & 1) == 0) {
#pragma unroll
                    for (int r = 0; r < 3; ++r) {
                        const ull u = *reinterpret_cast<const ull*>(bp + r * RSTRIDE);
                        const float v2s = bp[r * RSTRIDE + 2];
                        float lo_, hi_; unpack2(u, lo_, hi_);
                        p01[r] = u;
                        p12[r] = pack2(hi_, v2s);
                    }
                } else {
#pragma unroll
                    for (int r = 0; r < 3; ++r) {
                        const float v0 = bp[r * RSTRIDE];
                        const ull u = *reinterpret_cast<const ull*>(bp + r * RSTRIDE + 1);
                        float lo_, hi_; unpack2(u, lo_, hi_);
                        p01[r] = pack2(v0, lo_);
                        p12[r] = u;
                    }
                }
                const WPack wp = s_wt[l * 4 + k];
                fma2(acc[k][0], wp.w00, p01[0]);
                fma2(acc[k][0], wp.w01, p12[0]);
                fma2(acc[k][0], wp.w10, p01[1]);
                fma2(acc[k][0], wp.w11, p12[1]);
                fma2(acc[k][1], wp.w00, p01[1]);
                fma2(acc[k][1], wp.w01, p12[1]);
                fma2(acc[k][1], wp.w10, p01[2]);
                fma2(acc[k][1], wp.w11, p12[2]);
            }
        } else {
            // Rare fallback: offsets too spread for the smem tile — sample global.
            const float* img = imgb + (size_t)l * (H * W);
#pragma unroll
            for (int k = 0; k < NK; ++k) {
                const int2 off = s_off[l * 4 + k];
                float w00, w01, w10, w11, d0;
                unpack2(s_wt[l * 4 + k].w00, w00, d0);
                unpack2(s_wt[l * 4 + k].w01, w01, d0);
                unpack2(s_wt[l * 4 + k].w10, w10, d0);
                unpack2(s_wt[l * 4 + k].w11, w11, d0);
#pragma unroll
                for (int r = 0; r < 2; ++r) {
                    float s[2];
#pragma unroll
                    for (int c = 0; c < 2; ++c) {
                        const int iy0 = y0 + 2 * ty + r + off.y;
                        const int ix0 = x0 + 2 * tx + c + off.x;
                        const bool y0ok = (unsigned)iy0       < (unsigned)H;
                        const bool y1ok = (unsigned)(iy0 + 1) < (unsigned)H;
                        const bool x0ok = (unsigned)ix0       < (unsigned)W;
                        const bool x1ok = (unsigned)(ix0 + 1) < (unsigned)W;
                        const float v00 = (y0ok && x0ok) ? __ldg(&img[iy0 * W + ix0])           : 0.f;
                        const float v01 = (y0ok && x1ok) ? __ldg(&img[iy0 * W + ix0 + 1])       : 0.f;
                        const float v10 = (y1ok && x0ok) ? __ldg(&img[(iy0 + 1) * W + ix0])     : 0.f;
                        const float v11 = (y1ok && x1ok) ? __ldg(&img[(iy0 + 1) * W + ix0 + 1]) : 0.f;
                        s[c] = w00 * v00 + w01 * v01 + w10 * v10 + w11 * v11;
                    }
                    fma2(acc[k][r], one2, pack2(s[0], s[1]));
                }
            }
        }
    }

    // --- Write partials (float2 stores, 2 rows x 2 cols per k) ---
    float* gp = g_part + (size_t)chunk * (NB * NK * HO * WO)
                       + (size_t)b * (NK * HO * WO);
#pragma unroll
    for (int k = 0; k < NK; ++k) {
#pragma unroll
        for (int r = 0; r < 2; ++r) {
            float lo, hi;
            unpack2(acc[k][r], lo, hi);
            *reinterpret_cast<float2*>(
                &gp[(size_t)k * (HO * WO) + (y0 + 2 * ty + r) * WO + x0 + 2 * tx]) =
                make_float2(lo, hi);
        }
    }
}

// ---------------------------------------------------------------------------
// Pass 2: 15x15 PSF conv, 64x32 tile, 4x2 outputs/thread, f32x2 FMA.
// ---------------------------------------------------------------------------
#define P2TX 64
#define P2TY 32
#define P2RC 78      // region cols: 64 + 14
#define P2RR 46      // region rows: 32 + 14
#define P2S  80      // smem stride (float4-aligned)

__global__ void __launch_bounds__(256)
psf_conv_kernel(const float* __restrict__ psf, float* __restrict__ out)
{
    __shared__ float s_acc[P2RR * P2S];        // 14.7 KB
    __shared__ ull   s_psf2[KS * KS];          // 1.8 KB

    const int tid = threadIdx.x;
    const int p   = blockIdx.z;                // plane: b*4+k
    const int x0  = blockIdx.x * P2TX;
    const int y0  = blockIdx.y * P2TY;

    if (tid < KS * KS) {
        const float w = __ldg(&psf[tid]);
        s_psf2[tid] = pack2(w, w);
    }

    const float* p0 = g_part + (size_t)p * (HO * WO);
    const size_t  pstep = (size_t)(NB * NK) * (HO * WO);

    // Load region: cols 0..63
    {
        const int c  = tid & 63;
        const int gx = x0 + c - KR;
        const bool xok = (unsigned)gx < (unsigned)WO;
#pragma unroll 4
        for (int r = tid >> 6; r < P2RR; r += 4) {
            const int gy = y0 + r - KR;
            float v = 0.f;
            if (xok && (unsigned)gy < (unsigned)HO) {
                const int idx = gy * WO + gx;
                v = __ldg(&p0[idx]) + __ldg(&p0[idx + pstep])
                  + __ldg(&p0[idx + 2 * pstep]) + __ldg(&p0[idx + 3 * pstep]);
            }
            s_acc[r * P2S + c] = v;
        }
    }
    // Load region: cols 64..77
    {
        const int c  = 64 + (tid & 15);
        const int gx = x0 + c - KR;
        const bool cok = c < P2RC;
        const bool xok = cok && (unsigned)gx < (unsigned)WO;
#pragma unroll
        for (int r = tid >> 4; r < P2RR; r += 16) {
            const int gy = y0 + r - KR;
            float v = 0.f;
            if (xok && (unsigned)gy < (unsigned)HO) {
                const int idx = gy * WO + gx;
                v = __ldg(&p0[idx]) + __ldg(&p0[idx + pstep])
                  + __ldg(&p0[idx + 2 * pstep]) + __ldg(&p0[idx + 3 * pstep]);
            }
            if (cok) s_acc[r * P2S + c] = v;
        }
    }
    __syncthreads();

    const int tx = (tid & 15) * 4;   // 0..60
    const int ty = (tid >> 4) * 2;   // 0..30

    ull acc00 = 0, acc01 = 0, acc10 = 0, acc11 = 0;
    ull pp[17];

    auto load_pack = [&](int v) {
        float row[20];
        const float4* rp = reinterpret_cast<const float4*>(&s_acc[(ty + v) * P2S + tx]);
#pragma unroll
        for (int q = 0; q < 5; ++q) {
            const float4 t = rp[q];
            row[4*q+0] = t.x; row[4*q+1] = t.y; row[4*q+2] = t.z; row[4*q+3] = t.w;
        }
#pragma unroll
        for (int j = 0; j < 17; ++j) pp[j] = pack2(row[j], row[j+1]);
    };

    // v = 0: contributes only to output row 0 (ky = 0)
    load_pack(0);
#pragma unroll
    for (int kx = 0; kx < KS; ++kx) {
        const ull w = s_psf2[kx];
        fma2(acc00, w, pp[kx]);
        fma2(acc01, w, pp[kx + 2]);
    }
    // v = 1..14: contributes to both output rows
#pragma unroll 2
    for (int v = 1; v < KS; ++v) {
        load_pack(v);
#pragma unroll
        for (int kx = 0; kx < KS; ++kx) {
            const ull w0 = s_psf2[v * KS + kx];         // row 0, ky = v
            fma2(acc00, w0, pp[kx]);
            fma2(acc01, w0, pp[kx + 2]);
            const ull w1 = s_psf2[(v - 1) * KS + kx];   // row 1, ky = v-1
            fma2(acc10, w1, pp[kx]);
            fma2(acc11, w1, pp[kx + 2]);
        }
    }
    // v = 15: contributes only to output row 1 (ky = 14)
    load_pack(KS);
#pragma unroll
    for (int kx = 0; kx < KS; ++kx) {
        const ull w = s_psf2[(KS - 1) * KS + kx];
        fma2(acc10, w, pp[kx]);
        fma2(acc11, w, pp[kx + 2]);
    }

    float* op = out + (size_t)p * (HO * WO);
    const int ybase = y0 + ty;
    const int xbase = x0 + tx;
    float lo, hi;
    if (xbase < WO) {
        unpack2(acc00, lo, hi);
        *reinterpret_cast<float2*>(&op[ybase * WO + xbase]) = make_float2(lo, hi);
        unpack2(acc10, lo, hi);
        *reinterpret_cast<float2*>(&op[(ybase + 1) * WO + xbase]) = make_float2(lo, hi);
    }
    if (xbase + 2 < WO) {
        unpack2(acc01, lo, hi);
        *reinterpret_cast<float2*>(&op[ybase * WO + xbase + 2]) = make_float2(lo, hi);
        unpack2(acc11, lo, hi);
        *reinterpret_cast<float2*>(&op[(ybase + 1) * WO + xbase + 2]) = make_float2(lo, hi);
    }
}

// ---------------------------------------------------------------------------
extern "C" void kernel_launch(void* const* d_in, const int* in_sizes, int n_in,
                              void* d_out, int out_size)
{
    const float* cube = (const float*)d_in[0];   // (4, 96, 256, 256)
    const float* dx   = (const float*)d_in[1];   // (4, 96)
    const float* dy   = (const float*)d_in[2];   // (4, 96)
    const float* psf  = (const float*)d_in[3];   // (15, 15)
    float* out        = (float*)d_out;           // (4, 4, 288, 288)

    cudaFuncSetAttribute(shift_acc_kernel,
                         cudaFuncAttributeMaxDynamicSharedMemorySize, SMEM_DYN);

    dim3 g1(WO / TILE, HO / TILE, NB * NCHUNK);           // 9 x 9 x 16
    shift_acc_kernel<<<g1, 256, SMEM_DYN>>>(cube, dx, dy);

    dim3 g2((WO + P2TX - 1) / P2TX, HO / P2TY, NB * NK);  // 5 x 9 x 16
    psf_conv_kernel<<<g2, 256>>>(psf, out);
}